// round 5
// baseline (speedup 1.0000x reference)
#include <cuda_runtime.h>

// ---------------------------------------------------------------------------
// DeepESN on B200 (sm_100a): fused drive+recurrence, fp32 via packed f32x2 FMA.
//
// Decomposition:
//   grid = 128 persistent CTAs = 8 batch-groups (BC=32 rows) x 16 U-slices (NC=32 cols)
//   Each CTA holds its transposed weight slice [Win;Wrec][:, col0:col0+32] in SMEM
//   for the whole 512-step time loop. Per step:
//     z[:,slice] = x_t @ Win_s + H @ Wrec_s + b_s        (K = Din + 512)
//     h_new      = 0.1*h_old + 0.9*tanh(z)
//   H is double-buffered in global; a per-group (16 CTA) monotonic software
//   barrier separates steps. Groups (batch blocks) are fully independent.
//   1 CTA/SM (197.6 KB smem), 128 CTAs <= 148 SMs -> whole grid co-resident.
// ---------------------------------------------------------------------------

#define BB   256      // batch
#define TT   512      // time steps
#define UU   512      // units per layer
#define NCLS 10
#define NBG  8        // batch groups
#define BC   32       // batch rows per group
#define NSL  16       // U slices
#define NC   32       // U cols per slice
#define KPW  1028     // padded K stride for transposed weight rows (max Ktot=1024)
#define KPS  516      // padded K stride for staged activation rows (512)
#define NT   256      // threads per CTA

// Scratch (device globals: no allocation allowed)
__device__ float        g_S0[(size_t)BB * TT * UU];   // layer-0 states [B,T,U]
__device__ float        g_S1[(size_t)BB * TT * UU];   // layer-1 states [B,T,U]
__device__ float        g_H[2][BB * UU];              // double-buffered hidden state
__device__ float        g_R[BB * 3 * UU];             // concat(r0, r1, r2)
__device__ unsigned int g_bar[NBG];                   // per-group barrier counters

// Packed fp32 pair FMA: d = a*b + d  (2 FMAs/instr -> full fp32 rate on sm_100)
__device__ __forceinline__ void dfma2(unsigned long long& d,
                                      unsigned long long a,
                                      unsigned long long b) {
    asm("fma.rn.f32x2 %0, %1, %2, %0;" : "+l"(d) : "l"(a), "l"(b));
}
__device__ __forceinline__ float dsum2(unsigned long long v) {
    float lo, hi;
    asm("mov.b64 {%0, %1}, %2;" : "=f"(lo), "=f"(hi) : "l"(v));
    return lo + hi;
}

// acc[r] += sum_k stage[row_r][k] * WT[j][wbase+k], k in [0, 4*nC)
__device__ __forceinline__ void accum_phase(const float* __restrict__ sStage,
                                            const float* __restrict__ sWT,
                                            int j, int warp, int wbase, int nC,
                                            unsigned long long acc[4]) {
    const ulonglong2* w2 = reinterpret_cast<const ulonglong2*>(sWT + j * KPW + wbase);
    const ulonglong2* xr[4];
#pragma unroll
    for (int r = 0; r < 4; ++r)
        xr[r] = reinterpret_cast<const ulonglong2*>(sStage + (warp * 4 + r) * KPS);
#pragma unroll 4
    for (int c = 0; c < nC; ++c) {
        ulonglong2 w = w2[c];
#pragma unroll
        for (int r = 0; r < 4; ++r) {
            ulonglong2 a = xr[r][c];
            dfma2(acc[r], a.x, w.x);
            dfma2(acc[r], a.y, w.y);
        }
    }
}

__global__ void __launch_bounds__(NT, 1)
recur_kernel(const float* __restrict__ x0,
             const float* __restrict__ Win,
             const float* __restrict__ Wrec,
             const float* __restrict__ bias,
             int layer, int Din, int cwShift)
{
    extern __shared__ float smem[];
    float* sWT    = smem;               // [32][KPW] transposed weight slice
    float* sStage = smem + 32 * KPW;    // [32][KPS] staged x_t, then staged H

    const int tid  = threadIdx.x;
    const int j    = tid & 31;          // column within slice
    const int warp = tid >> 5;          // 0..7 -> rows warp*4 .. warp*4+3
    const int bid  = blockIdx.x;
    const int grp  = bid >> 4;          // batch group 0..7
    const int sl   = bid & 15;          // U slice 0..15
    const int b0   = grp * BC;
    const int col0 = sl * NC;
    const int col  = col0 + j;
    const int Ktot = Din + UU;

    const float* xin  = (layer == 0) ? x0 : ((layer == 1) ? g_S0 : g_S1);
    float*       sout = (layer == 0) ? g_S0 : ((layer == 1) ? g_S1 : (float*)0);

    // Load transposed weight slice: sWT[j][k] = (k<Din ? Win : Wrec)[k][col0+j]
    // Coalesced over jj (32 consecutive floats per row of the global weight).
    for (int idx = tid; idx < 32 * Ktot; idx += NT) {
        int jj = idx & 31;
        int kk = idx >> 5;
        float v = (kk < Din) ? Win[(size_t)kk * UU + col0 + jj]
                             : Wrec[(size_t)(kk - Din) * UU + col0 + jj];
        sWT[jj * KPW + kk] = v;
    }
    const float bj = bias[col];
    __syncthreads();

    const int cW    = Din >> 2;     // float4s per input row
    const int nvA   = BC * cW;
    const int maskW = cW - 1;
    unsigned int tgt = 0;           // running barrier target for this group

    for (int t = 0; t < TT; ++t) {
        const int p = t & 1;

        // ---- Phase A: stage x_t rows [BC x Din] into sStage ----
        for (int idx = tid; idx < nvA; idx += NT) {
            int i = idx >> cwShift;
            int c = idx & maskW;
            const float4* src = reinterpret_cast<const float4*>(
                xin + ((size_t)(b0 + i) * TT + t) * Din);
            reinterpret_cast<float4*>(sStage + i * KPS)[c] = src[c];
        }
        __syncthreads();

        unsigned long long acc[4] = {0ull, 0ull, 0ull, 0ull};
        accum_phase(sStage, sWT, j, warp, 0, Din >> 2, acc);
        __syncthreads();   // finished reading x stage before overwrite

        // ---- Phase B: stage H rows [BC x 512]. Bypass L1: these lines are
        //      re-read every 2 steps within one launch and must come from L2,
        //      where the previous step's writes are visible. ----
        for (int idx = tid; idx < BC * (UU / 4); idx += NT) {
            int i = idx >> 7;
            int c = idx & 127;
            const float4* src = reinterpret_cast<const float4*>(
                g_H[p] + (size_t)(b0 + i) * UU);
            float4 v = __ldcg(src + c);
            reinterpret_cast<float4*>(sStage + i * KPS)[c] = v;
        }
        __syncthreads();

        accum_phase(sStage, sWT, j, warp, Din, UU / 4, acc);

        // ---- Update + store ----
#pragma unroll
        for (int r = 0; r < 4; ++r) {
            int    i    = warp * 4 + r;
            float  z    = dsum2(acc[r]) + bj;
            float  hold = sStage[i * KPS + col];   // staged H holds all 512 cols
            float  hnew = hold * 0.1f + tanhf(z) * 0.9f;
            size_t gi   = (size_t)(b0 + i);
            g_H[p ^ 1][gi * UU + col] = hnew;
            if (sout) sout[(gi * TT + t) * UU + col] = hnew;
            if (t == TT - 1) g_R[gi * (3 * UU) + (size_t)layer * UU + col] = hnew;
        }

        // ---- Per-group barrier (16 CTAs), monotonic counter. ----
        if (t < TT - 1) {
            __threadfence();           // release h_new stores to gpu scope
            __syncthreads();           // all threads' stores fenced before arrive
            tgt += NSL;
            if (tid == 0) {
                atomicAdd(&g_bar[grp], 1u);
                unsigned int v;
                do {
                    asm volatile("ld.acquire.gpu.u32 %0, [%1];"
                                 : "=r"(v) : "l"(&g_bar[grp]));
                    if (v >= tgt) break;
                    __nanosleep(32);
                } while (true);
            }
            __syncthreads();           // also guards sStage overwrite next step
        }
    }
}

__global__ void init_kernel() {
    int idx = blockIdx.x * blockDim.x + threadIdx.x;
    if (idx < 2 * BB * UU) ((float*)g_H)[idx] = 0.0f;
    if (idx < NBG) g_bar[idx] = 0u;
}

__global__ void readout_kernel(const float* __restrict__ Wout,
                               const float* __restrict__ bout,
                               float* __restrict__ out) {
    __shared__ float red[NCLS][NT];
    int b = blockIdx.x, tid = threadIdx.x;
    float part[NCLS];
#pragma unroll
    for (int c = 0; c < NCLS; ++c) part[c] = 0.0f;
    for (int k = tid; k < 3 * UU; k += NT) {
        float r = g_R[(size_t)b * 3 * UU + k];
#pragma unroll
        for (int c = 0; c < NCLS; ++c) part[c] += r * Wout[k * NCLS + c];
    }
#pragma unroll
    for (int c = 0; c < NCLS; ++c) red[c][tid] = part[c];
    __syncthreads();
    if (tid < NCLS) {
        float s = 0.0f;
        for (int i = 0; i < NT; ++i) s += red[tid][i];
        out[b * NCLS + tid] = s + bout[tid];
    }
}

extern "C" void kernel_launch(void* const* d_in, const int* in_sizes, int n_in,
                              void* d_out, int out_size) {
    (void)in_sizes; (void)n_in; (void)out_size;
    const float* x    = (const float*)d_in[0];
    const float* Win0 = (const float*)d_in[1];
    const float* W0   = (const float*)d_in[2];
    const float* b0   = (const float*)d_in[3];
    const float* Win1 = (const float*)d_in[4];
    const float* W1   = (const float*)d_in[5];
    const float* b1   = (const float*)d_in[6];
    const float* Win2 = (const float*)d_in[7];
    const float* W2   = (const float*)d_in[8];
    const float* b2   = (const float*)d_in[9];
    const float* Wout = (const float*)d_in[10];
    const float* bout = (const float*)d_in[11];
    float* out = (float*)d_out;

    const int smem = (32 * KPW + 32 * KPS) * (int)sizeof(float);  // 197,632 B
    static int attr_done = 0;
    if (!attr_done) {
        cudaFuncSetAttribute(recur_kernel,
                             cudaFuncAttributeMaxDynamicSharedMemorySize, smem);
        attr_done = 1;
    }

    init_kernel<<<1024, NT>>>();
    recur_kernel<<<NBG * NSL, NT, smem>>>(x, Win0, W0, b0, 0, 64, 4);
    init_kernel<<<1024, NT>>>();
    recur_kernel<<<NBG * NSL, NT, smem>>>(x, Win1, W1, b1, 1, 512, 7);
    init_kernel<<<1024, NT>>>();
    recur_kernel<<<NBG * NSL, NT, smem>>>(x, Win2, W2, b2, 2, 512, 7);
    readout_kernel<<<BB, NT>>>(Wout, bout, out);
}

// round 7
// speedup vs baseline: 1.8557x; 1.8557x over previous
#include <cuda_runtime.h>

// ---------------------------------------------------------------------------
// DeepESN on B200 (sm_100a), round 7 (= round-6 algorithm, host-side hardened:
// no cudaGetSymbolAddress, attribute set only on first uncaptured call).
//   Stage 1: drive GEMM  u = X @ Win + b   (fully parallel, f32x2-packed)
//   Stage 2: recurrence  h' = 0.1 h + 0.9 tanh(u_t + h @ Wrec)
//     128 persistent CTAs = 16 batch-groups (16 rows) x 8 col-slices (64 cols)
//     8 warps = 2 row-groups x 4 k-chunks; lane = 2 cols x 8 rows (f32x2 accs)
//     Wrec slice (64 x 512) SMEM-resident for all 512 steps.
//     Per-group (8 CTA) monotonic barrier; H double-buffered in global.
// ---------------------------------------------------------------------------

#define BB   256
#define TT   512
#define UU   512
#define NCLS 10

// recurrence tiling
#define NGRP 16        // batch groups
#define BCR  16        // rows per group
#define NSLC 8         // col slices
#define NCOL 64        // cols per slice
#define SSTR 516       // padded k stride (512 + 4)
#define RSLOT 20       // padded reduction slot
#define NT   256

// drive GEMM tiling
#define ASTR 130
#define BSTR 68

// device scratch (allocation is forbidden; __device__ globals are the path)
__device__ float        g_S0[(size_t)BB * TT * UU];
__device__ float        g_S1[(size_t)BB * TT * UU];
__device__ float        g_U [(size_t)BB * TT * UU];
__device__ float        g_H[2][BB * UU];
__device__ float        g_R[BB * 3 * UU];
__device__ unsigned int g_bar[NGRP];

__device__ __forceinline__ void dfma2(unsigned long long& d,
                                      unsigned long long a,
                                      unsigned long long b) {
    asm("fma.rn.f32x2 %0, %1, %2, %0;" : "+l"(d) : "l"(a), "l"(b));
}
__device__ __forceinline__ float dsum2(unsigned long long v) {
    float lo, hi;
    asm("mov.b64 {%0, %1}, %2;" : "=f"(lo), "=f"(hi) : "l"(v));
    return lo + hi;
}
__device__ __forceinline__ unsigned long long pk2(float x) {
    unsigned long long r;
    asm("mov.b64 %0, {%1, %1};" : "=l"(r) : "f"(x));
    return r;
}
__device__ __forceinline__ void upk2(unsigned long long v, float& lo, float& hi) {
    asm("mov.b64 {%0, %1}, %2;" : "=f"(lo), "=f"(hi) : "l"(v));
}

// ============================================================================
// Drive GEMM: g_U[M,512] = A[M,K] @ W[K,512] + bias.  M = BB*TT, K in {64,512}.
// A selected in-kernel: layer 0 -> x (arg), layer 1 -> g_S0, layer 2 -> g_S1.
// Tile 128x64, 256 threads, thread = 8 rows x 4 cols, rows packed as f32x2.
// ============================================================================
__global__ void __launch_bounds__(NT)
drive_gemm(const float* __restrict__ x, const float* __restrict__ W,
           const float* __restrict__ bias, int K, int layer)
{
    __shared__ float As[16 * ASTR];   // transposed: As[k][row]
    __shared__ float Bs[16 * BSTR];   // Bs[k][col]

    const float* A = (layer == 0) ? x : ((layer == 1) ? g_S0 : g_S1);
    float*       C = g_U;

    const int tid = threadIdx.x;
    const int tx  = tid & 15;         // col group (4 cols)
    const int ty  = tid >> 4;         // row group (8 rows)
    const int m0  = blockIdx.y * 128;
    const int n0  = blockIdx.x * 64;

    unsigned long long acc[4][4];     // [rowpair][col]
#pragma unroll
    for (int p = 0; p < 4; ++p)
#pragma unroll
        for (int c = 0; c < 4; ++c) acc[p][c] = 0ull;

    for (int kt = 0; kt < K; kt += 16) {
        // stage A: 128 rows x 16 k, transposed into As[k][row]
#pragma unroll
        for (int it = 0; it < 2; ++it) {
            int idx = tid + it * NT;
            int row = idx >> 2, c4 = idx & 3;
            float4 v = __ldg(reinterpret_cast<const float4*>(
                                 A + (size_t)(m0 + row) * K + kt) + c4);
            As[(c4 * 4 + 0) * ASTR + row] = v.x;
            As[(c4 * 4 + 1) * ASTR + row] = v.y;
            As[(c4 * 4 + 2) * ASTR + row] = v.z;
            As[(c4 * 4 + 3) * ASTR + row] = v.w;
        }
        // stage B: 16 k x 64 cols
        {
            int k = tid >> 4, c4 = tid & 15;
            float4 v = __ldg(reinterpret_cast<const float4*>(
                                 W + (size_t)(kt + k) * UU + n0) + c4);
            *reinterpret_cast<float4*>(Bs + k * BSTR + c4 * 4) = v;
        }
        __syncthreads();

#pragma unroll
        for (int k = 0; k < 16; ++k) {
            unsigned long long a[4];
#pragma unroll
            for (int p = 0; p < 4; ++p)
                a[p] = *reinterpret_cast<const unsigned long long*>(
                           As + k * ASTR + ty * 8 + 2 * p);
            float4 b = *reinterpret_cast<const float4*>(Bs + k * BSTR + tx * 4);
            unsigned long long bb[4] = {pk2(b.x), pk2(b.y), pk2(b.z), pk2(b.w)};
#pragma unroll
            for (int p = 0; p < 4; ++p) {
                dfma2(acc[p][0], a[p], bb[0]);
                dfma2(acc[p][1], a[p], bb[1]);
                dfma2(acc[p][2], a[p], bb[2]);
                dfma2(acc[p][3], a[p], bb[3]);
            }
        }
        __syncthreads();
    }

    float4 bv = __ldg(reinterpret_cast<const float4*>(bias + n0 + tx * 4));
#pragma unroll
    for (int p = 0; p < 4; ++p) {
        float4 lo, hi;
        upk2(acc[p][0], lo.x, hi.x);
        upk2(acc[p][1], lo.y, hi.y);
        upk2(acc[p][2], lo.z, hi.z);
        upk2(acc[p][3], lo.w, hi.w);
        lo.x += bv.x; lo.y += bv.y; lo.z += bv.z; lo.w += bv.w;
        hi.x += bv.x; hi.y += bv.y; hi.z += bv.z; hi.w += bv.w;
        size_t r0 = (size_t)(m0 + ty * 8 + 2 * p) * UU + n0 + tx * 4;
        *reinterpret_cast<float4*>(C + r0)      = lo;
        *reinterpret_cast<float4*>(C + r0 + UU) = hi;
    }
}

// ============================================================================
// Recurrence kernel (drive precomputed in g_U; K = 512 recurrent only).
// sout selected in-kernel: layer 0 -> g_S0, layer 1 -> g_S1, layer 2 -> none.
// ============================================================================
__global__ void __launch_bounds__(NT, 1)
recur_kernel(const float* __restrict__ Wrec, int layer)
{
    extern __shared__ float smem[];
    float* sWT  = smem;                       // [64][SSTR] transposed Wrec slice
    float* sSt  = smem + NCOL * SSTR;         // [16][SSTR] staged H rows
    float* sRed = sSt + BCR * SSTR;           // [4][64*RSLOT] k-chunk partials

    const float* u    = g_U;
    float*       sout = (layer == 0) ? g_S0 : ((layer == 1) ? g_S1 : (float*)0);

    const int tid  = threadIdx.x;
    const int lane = tid & 31;
    const int wid  = tid >> 5;
    const int rg   = wid & 1;                 // row group: rows rg*8 .. rg*8+7
    const int kc   = wid >> 1;                // k chunk: [kc*128, kc*128+128)
    const int bid  = blockIdx.x;
    const int grp  = bid >> 3;                // 16 batch groups
    const int sl   = bid & 7;                 // 8 col slices
    const int b0   = grp * BCR;
    const int col0 = sl * NCOL;
    const int kbase = kc * 128;

    // Load transposed weight slice: sWT[c][k] = Wrec[k][col0+c] (coalesced in c)
    for (int idx = tid; idx < NCOL * UU; idx += NT) {
        int c = idx & 63, k = idx >> 6;
        sWT[c * SSTR + k] = Wrec[(size_t)k * UU + col0 + c];
    }
    __syncthreads();

    unsigned int tgt = 0;

    for (int t = 0; t < TT; ++t) {
        const int p = t & 1;

        // stage H rows [16 x 512]; L1 bypass (re-read across steps in-launch)
        for (int idx = tid; idx < BCR * 128; idx += NT) {
            int i = idx >> 7, c = idx & 127;
            float4 v = __ldcg(reinterpret_cast<const float4*>(
                                  g_H[p] + (size_t)(b0 + i) * UU) + c);
            reinterpret_cast<float4*>(sSt + i * SSTR)[c] = v;
        }
        __syncthreads();

        unsigned long long acc[8][2];
#pragma unroll
        for (int r = 0; r < 8; ++r) { acc[r][0] = 0ull; acc[r][1] = 0ull; }

        const ulonglong2* w0p = reinterpret_cast<const ulonglong2*>(
            sWT + lane * SSTR + kbase);
        const ulonglong2* w1p = reinterpret_cast<const ulonglong2*>(
            sWT + (lane + 32) * SSTR + kbase);
        const float* arow = sSt + rg * 8 * SSTR + kbase;

#pragma unroll 2
        for (int c = 0; c < 32; ++c) {
            ulonglong2 w0 = w0p[c];
            ulonglong2 w1 = w1p[c];
#pragma unroll
            for (int r = 0; r < 8; ++r) {
                ulonglong2 a = *reinterpret_cast<const ulonglong2*>(
                    arow + r * SSTR + 4 * c);
                dfma2(acc[r][0], a.x, w0.x);
                dfma2(acc[r][0], a.y, w0.y);
                dfma2(acc[r][1], a.x, w1.x);
                dfma2(acc[r][1], a.y, w1.y);
            }
        }

        // write k-chunk partials (padded slots, 16B vector stores)
        {
            float* myred = sRed + (size_t)kc * (64 * RSLOT)
                                + (rg * 32 + lane) * RSLOT;
            float4 v;
#pragma unroll
            for (int q = 0; q < 4; ++q) {           // slot = r*2+cc, packed x4
                int r = q * 2;
                v.x = dsum2(acc[r][0]);
                v.y = dsum2(acc[r][1]);
                v.z = dsum2(acc[r + 1][0]);
                v.w = dsum2(acc[r + 1][1]);
                *reinterpret_cast<float4*>(myred + q * 4) = v;
            }
        }
        __syncthreads();

        // finalize: each thread owns 4 consecutive outputs
        {
            int o0   = tid * 4;
            int i    = o0 >> 6;           // row 0..15
            int cloc = o0 & 63;           // col base (mult of 4)
            int r    = i & 7;
            int rg2  = i >> 3;
            size_t m = (size_t)(b0 + i) * TT + t;
            float4 uv = __ldg(reinterpret_cast<const float4*>(
                                  u + m * UU + col0 + cloc));
            float4 hold = *reinterpret_cast<const float4*>(
                sSt + i * SSTR + col0 + cloc);
            float zq[4] = {uv.x, uv.y, uv.z, uv.w};
            float hq[4] = {hold.x, hold.y, hold.z, hold.w};
            float4 hn;
            float* hnp = &hn.x;
#pragma unroll
            for (int q = 0; q < 4; ++q) {
                int c  = cloc + q;
                int cc = c >> 5, jj = c & 31;
                int base = (rg2 * 32 + jj) * RSLOT + (r * 2 + cc);
                float z = zq[q];
#pragma unroll
                for (int k2 = 0; k2 < 4; ++k2)
                    z += sRed[(size_t)k2 * (64 * RSLOT) + base];
                hnp[q] = hq[q] * 0.1f + 0.9f * tanhf(z);
            }
            size_t gh = (size_t)(b0 + i) * UU + col0 + cloc;
            *reinterpret_cast<float4*>(g_H[p ^ 1] + gh) = hn;
            if (sout)
                *reinterpret_cast<float4*>(sout + m * UU + col0 + cloc) = hn;
            if (t == TT - 1)
                *reinterpret_cast<float4*>(
                    g_R + (size_t)(b0 + i) * (3 * UU) + layer * UU
                        + col0 + cloc) = hn;
        }

        // per-group barrier (8 CTAs), monotonic counter
        if (t < TT - 1) {
            __threadfence();
            __syncthreads();
            tgt += NSLC;
            if (tid == 0) {
                atomicAdd(&g_bar[grp], 1u);
                unsigned int v;
                do {
                    asm volatile("ld.acquire.gpu.u32 %0, [%1];"
                                 : "=r"(v) : "l"(&g_bar[grp]));
                    if (v >= tgt) break;
                    __nanosleep(32);
                } while (true);
            }
            __syncthreads();
        }
    }
}

__global__ void init_kernel() {
    int idx = blockIdx.x * blockDim.x + threadIdx.x;
    if (idx < 2 * BB * UU) ((float*)g_H)[idx] = 0.0f;
    if (idx < NGRP) g_bar[idx] = 0u;
}

__global__ void readout_kernel(const float* __restrict__ Wout,
                               const float* __restrict__ bout,
                               float* __restrict__ out) {
    __shared__ float red[NCLS][NT];
    int b = blockIdx.x, tid = threadIdx.x;
    float part[NCLS];
#pragma unroll
    for (int c = 0; c < NCLS; ++c) part[c] = 0.0f;
    for (int k = tid; k < 3 * UU; k += NT) {
        float r = g_R[(size_t)b * 3 * UU + k];
#pragma unroll
        for (int c = 0; c < NCLS; ++c) part[c] += r * Wout[k * NCLS + c];
    }
#pragma unroll
    for (int c = 0; c < NCLS; ++c) red[c][tid] = part[c];
    __syncthreads();
    if (tid < NCLS) {
        float s = 0.0f;
        for (int i = 0; i < NT; ++i) s += red[tid][i];
        out[b * NCLS + tid] = s + bout[tid];
    }
}

extern "C" void kernel_launch(void* const* d_in, const int* in_sizes, int n_in,
                              void* d_out, int out_size) {
    (void)in_sizes; (void)n_in; (void)out_size;
    const float* x    = (const float*)d_in[0];
    const float* Win0 = (const float*)d_in[1];
    const float* W0   = (const float*)d_in[2];
    const float* b0   = (const float*)d_in[3];
    const float* Win1 = (const float*)d_in[4];
    const float* W1   = (const float*)d_in[5];
    const float* b1   = (const float*)d_in[6];
    const float* Win2 = (const float*)d_in[7];
    const float* W2   = (const float*)d_in[8];
    const float* b2   = (const float*)d_in[9];
    const float* Wout = (const float*)d_in[10];
    const float* bout = (const float*)d_in[11];
    float* out = (float*)d_out;

    // recurrence smem: weights 64x516 + stage 16x516 + red 4x64x20 = 185,600 B
    const int smem = (NCOL * SSTR + BCR * SSTR + 4 * 64 * RSLOT) * (int)sizeof(float);
    static int attr_done = 0;           // first call is uncaptured; replays skip
    if (!attr_done) {
        cudaFuncSetAttribute(recur_kernel,
                             cudaFuncAttributeMaxDynamicSharedMemorySize, smem);
        attr_done = 1;
    }

    const dim3 gemm_grid(UU / 64, (BB * TT) / 128);

    // layer 0
    init_kernel<<<1024, NT>>>();
    drive_gemm<<<gemm_grid, NT>>>(x, Win0, b0, 64, 0);
    recur_kernel<<<NGRP * NSLC, NT, smem>>>(W0, 0);

    // layer 1
    init_kernel<<<1024, NT>>>();
    drive_gemm<<<gemm_grid, NT>>>(x, Win1, b1, 512, 1);
    recur_kernel<<<NGRP * NSLC, NT, smem>>>(W1, 1);

    // layer 2
    init_kernel<<<1024, NT>>>();
    drive_gemm<<<gemm_grid, NT>>>(x, Win2, b2, 512, 2);
    recur_kernel<<<NGRP * NSLC, NT, smem>>>(W2, 2);

    readout_kernel<<<BB, NT>>>(Wout, bout, out);
}